// round 1
// baseline (speedup 1.0000x reference)
#include <cuda_runtime.h>
#include <math.h>
#include <stdint.h>

// Problem constants (fixed by the dataset)
#define NMAX   50000
#define EMAX   600000
#define HIDW   256
#define OUTW   352
#define OUTT   349
#define MAXNTOT 272

// ---------------- scratch (device globals; no allocation allowed) ----------
__device__ int   g_deg[NMAX];
__device__ float g_dinv[NMAX];
__device__ int   g_off[NMAX + 1];
__device__ int   g_cur[NMAX];
__device__ int   g_adj[EMAX];
__device__ float g_lin[(size_t)NMAX * MAXNTOT];   // [N, NBF+96] per layer
__device__ float g_hA[(size_t)NMAX * HIDW];
__device__ float g_hB[(size_t)NMAX * HIDW];
__device__ float g_hO[(size_t)NMAX * OUTW];

// ---------------- CSR build -------------------------------------------------
__global__ void k_zero(int n) {
    int i = blockIdx.x * blockDim.x + threadIdx.x;
    if (i < n) g_deg[i] = 0;
}

__global__ void k_deg(const int* __restrict__ row, int e) {
    int i = blockIdx.x * blockDim.x + threadIdx.x;
    if (i < e) atomicAdd(&g_deg[row[i]], 1);
}

__global__ void k_dinv(int n) {
    int i = blockIdx.x * blockDim.x + threadIdx.x;
    if (i < n) {
        int d = g_deg[i];
        g_dinv[i] = (d > 0) ? rsqrtf((float)d) : 0.0f;
    }
}

__global__ void k_scan(int n, int total) {
    __shared__ int sums[1024];
    int t = threadIdx.x;
    int chunk = (n + 1023) / 1024;
    int lo = t * chunk;
    int hi = lo + chunk; if (hi > n) hi = n;
    int s = 0;
    for (int i = lo; i < hi; i++) s += g_deg[i];
    sums[t] = s;
    __syncthreads();
    // Hillis-Steele inclusive scan
    for (int d = 1; d < 1024; d <<= 1) {
        int v = (t >= d) ? sums[t - d] : 0;
        __syncthreads();
        sums[t] += v;
        __syncthreads();
    }
    int run = (t == 0) ? 0 : sums[t - 1];
    for (int i = lo; i < hi; i++) {
        g_off[i] = run;
        g_cur[i] = run;
        run += g_deg[i];
    }
    if (t == 0) g_off[n] = total;
}

__global__ void k_scatter(const int* __restrict__ row, const int* __restrict__ col, int e) {
    int i = blockIdx.x * blockDim.x + threadIdx.x;
    if (i < e) {
        int r = row[i];
        int p = atomicAdd(&g_cur[r], 1);
        g_adj[p] = col[i];
    }
}

// ---------------- fused GEMM: lin = h @ [Wb | Wc] + [0 | bc] ----------------
// 128x128 block tile, BK=16, 256 threads, 8x8 micro-tile per thread.
__global__ __launch_bounds__(256)
void k_gemm(const float* __restrict__ A,
            const float* __restrict__ Wb,
            const float* __restrict__ Wc,
            const float* __restrict__ bc,
            float* __restrict__ C,
            int M, int K, int NBF, int Ntot)
{
    __shared__ float As[16][128 + 4];
    __shared__ float Bs[16][128];
    const int bm = blockIdx.y * 128;
    const int bn = blockIdx.x * 128;
    const int tid = threadIdx.x;
    const int tx = tid & 15;    // 16 column groups
    const int ty = tid >> 4;    // 16 row groups
    const int cw = Ntot - NBF;  // 96

    float acc[8][8];
#pragma unroll
    for (int r = 0; r < 8; r++)
#pragma unroll
        for (int c = 0; c < 8; c++) acc[r][c] = 0.0f;

    for (int k0 = 0; k0 < K; k0 += 16) {
        // load A tile (128 x 16)
#pragma unroll
        for (int i = 0; i < 8; i++) {
            int idx = tid + i * 256;
            int m = idx >> 4, kk = idx & 15;
            int gm = bm + m;
            As[kk][m] = (gm < M) ? A[(size_t)gm * K + k0 + kk] : 0.0f;
        }
        // load B tile (16 x 128) from virtual concat [Wb | Wc]
#pragma unroll
        for (int i = 0; i < 8; i++) {
            int idx = tid + i * 256;
            int kk = idx >> 7, nn = idx & 127;
            int gn = bn + nn;
            int gk = k0 + kk;
            float v = 0.0f;
            if (gn < NBF)       v = Wb[(size_t)gk * NBF + gn];
            else if (gn < Ntot) v = Wc[(size_t)gk * cw + (gn - NBF)];
            Bs[kk][nn] = v;
        }
        __syncthreads();
#pragma unroll
        for (int kk = 0; kk < 16; kk++) {
            float a[8], b[8];
#pragma unroll
            for (int r = 0; r < 8; r++) a[r] = As[kk][ty * 8 + r];
#pragma unroll
            for (int c = 0; c < 8; c++) b[c] = Bs[kk][tx * 8 + c];
#pragma unroll
            for (int r = 0; r < 8; r++)
#pragma unroll
                for (int c = 0; c < 8; c++)
                    acc[r][c] = fmaf(a[r], b[c], acc[r][c]);
        }
        __syncthreads();
    }

#pragma unroll
    for (int r = 0; r < 8; r++) {
        int gm = bm + ty * 8 + r;
        if (gm >= M) continue;
#pragma unroll
        for (int c = 0; c < 8; c++) {
            int gn = bn + tx * 8 + c;
            if (gn < Ntot) {
                float v = acc[r][c];
                if (gn >= NBF) v += bc[gn - NBF];
                C[(size_t)gm * Ntot + gn] = v;
            }
        }
    }
}

// ---------------- fused aggregation + combine + bias (+relu) ----------------
// One warp per node. 3 aggregators (symnorm, mean, max) over NBF columns,
// then out[h*F+f] = b[c] + sum_k comb[h*12+k] * agg[k*F+f].
template<int NBF, int F, bool RELU>
__global__ __launch_bounds__(256)
void k_agg(const float* __restrict__ lin, int stride,
           const float* __restrict__ bias,
           float* __restrict__ out, int n)
{
    constexpr int HF  = 8 * F;            // output width
    constexpr int C4  = (NBF + 127) / 128; // float4 slots per lane
    constexpr int NF4 = NBF / 4;           // float4 per row
    __shared__ float agg_s[8][3 * NBF];
    __shared__ float comb_s[8][96];

    int gw   = (blockIdx.x * 256 + threadIdx.x) >> 5;
    int lane = threadIdx.x & 31;
    int lw   = threadIdx.x >> 5;
    if (gw >= n) return;

    int s = g_off[gw], e = g_off[gw + 1];
    int deg = e - s;

    float4 vsym[C4], vsum[C4], vmax[C4];
#pragma unroll
    for (int q = 0; q < C4; q++) {
        vsym[q] = make_float4(0.f, 0.f, 0.f, 0.f);
        vsum[q] = make_float4(0.f, 0.f, 0.f, 0.f);
        vmax[q] = make_float4(-INFINITY, -INFINITY, -INFINITY, -INFINITY);
    }

    for (int t = s; t < e; t++) {
        int c = g_adj[t];
        float dv = g_dinv[c];
        const float4* src = reinterpret_cast<const float4*>(lin + (size_t)c * stride);
#pragma unroll
        for (int q = 0; q < C4; q++) {
            int i4 = lane + q * 32;
            if (C4 > 1 && i4 >= NF4) break;
            float4 v = src[i4];
            vsym[q].x += dv * v.x; vsym[q].y += dv * v.y;
            vsym[q].z += dv * v.z; vsym[q].w += dv * v.w;
            vsum[q].x += v.x; vsum[q].y += v.y;
            vsum[q].z += v.z; vsum[q].w += v.w;
            vmax[q].x = fmaxf(vmax[q].x, v.x); vmax[q].y = fmaxf(vmax[q].y, v.y);
            vmax[q].z = fmaxf(vmax[q].z, v.z); vmax[q].w = fmaxf(vmax[q].w, v.w);
        }
    }

    float dn   = g_dinv[gw];
    float invd = (deg > 0) ? (1.0f / (float)deg) : 0.0f;

    float4* arow0 = reinterpret_cast<float4*>(&agg_s[lw][0]);
    float4* arow1 = reinterpret_cast<float4*>(&agg_s[lw][NBF]);
    float4* arow2 = reinterpret_cast<float4*>(&agg_s[lw][2 * NBF]);
#pragma unroll
    for (int q = 0; q < C4; q++) {
        int i4 = lane + q * 32;
        if (C4 > 1 && i4 >= NF4) break;
        float4 sy = vsym[q];
        sy.x *= dn; sy.y *= dn; sy.z *= dn; sy.w *= dn;
        float4 me = vsum[q];
        me.x *= invd; me.y *= invd; me.z *= invd; me.w *= invd;
        float4 mx = vmax[q];
        if (deg == 0) mx = make_float4(0.f, 0.f, 0.f, 0.f);
        arow0[i4] = sy;
        arow1[i4] = me;
        arow2[i4] = mx;
    }

    // comb row (96 floats) into smem
    const float* comb = lin + (size_t)gw * stride + NBF;
    comb_s[lw][lane]      = comb[lane];
    comb_s[lw][lane + 32] = comb[lane + 32];
    comb_s[lw][lane + 64] = comb[lane + 64];
    __syncwarp();

#pragma unroll
    for (int c = lane; c < HF; c += 32) {
        int h = c / F, f = c % F;
        float v = bias[c];
        const float* cb = &comb_s[lw][h * 12];
        const float* ag = &agg_s[lw][0];
#pragma unroll
        for (int k = 0; k < 12; k++) v = fmaf(cb[k], ag[k * F + f], v);
        if (RELU) v = fmaxf(v, 0.0f);
        out[(size_t)gw * HF + c] = v;
    }
}

// ---------------- log_softmax over first OUTT cols of [N, OUTW] -------------
__global__ __launch_bounds__(256)
void k_lsm(const float* __restrict__ in, float* __restrict__ out, int n)
{
    int gw   = (blockIdx.x * 256 + threadIdx.x) >> 5;
    int lane = threadIdx.x & 31;
    if (gw >= n) return;
    const float* r = in + (size_t)gw * OUTW;
    float v[11];
    float m = -INFINITY;
#pragma unroll
    for (int i = 0; i < 11; i++) {
        int c = lane + i * 32;
        v[i] = (c < OUTT) ? r[c] : -INFINITY;
        m = fmaxf(m, v[i]);
    }
#pragma unroll
    for (int o = 16; o; o >>= 1) m = fmaxf(m, __shfl_xor_sync(0xffffffffu, m, o));
    float s = 0.0f;
#pragma unroll
    for (int i = 0; i < 11; i++) s += expf(v[i] - m);   // exp(-inf)=0 for padding
#pragma unroll
    for (int o = 16; o; o >>= 1) s += __shfl_xor_sync(0xffffffffu, s, o);
    float l = m + logf(s);
#pragma unroll
    for (int i = 0; i < 11; i++) {
        int c = lane + i * 32;
        if (c < OUTT) out[(size_t)gw * OUTT + c] = v[i] - l;
    }
}

// ---------------- launch ----------------------------------------------------
extern "C" void kernel_launch(void* const* d_in, const int* in_sizes, int n_in,
                              void* d_out, int out_size)
{
    const float* x   = (const float*)d_in[0];
    const int*   ei  = (const int*)d_in[1];
    int N = in_sizes[0] / 128;
    int E = in_sizes[1] / 2;
    if (N > NMAX) N = NMAX;
    if (E > EMAX) E = EMAX;
    const int* row = ei;
    const int* col = ei + E;

    const float* Wb0 = (const float*)d_in[2];
    const float* Wc0 = (const float*)d_in[3];
    const float* bc0 = (const float*)d_in[4];
    const float* b0  = (const float*)d_in[5];
    const float* Wb1 = (const float*)d_in[6];
    const float* Wc1 = (const float*)d_in[7];
    const float* bc1 = (const float*)d_in[8];
    const float* b1  = (const float*)d_in[9];
    const float* Wb2 = (const float*)d_in[10];
    const float* Wc2 = (const float*)d_in[11];
    const float* bc2 = (const float*)d_in[12];
    const float* b2  = (const float*)d_in[13];

    float* lin; float* hA; float* hB; float* hO;
    cudaGetSymbolAddress((void**)&lin, g_lin);
    cudaGetSymbolAddress((void**)&hA,  g_hA);
    cudaGetSymbolAddress((void**)&hB,  g_hB);
    cudaGetSymbolAddress((void**)&hO,  g_hO);

    const int T = 256;
    // CSR build
    k_zero   <<<(N + T - 1) / T, T>>>(N);
    k_deg    <<<(E + T - 1) / T, T>>>(row, E);
    k_dinv   <<<(N + T - 1) / T, T>>>(N);
    k_scan   <<<1, 1024>>>(N, E);
    k_scatter<<<(E + T - 1) / T, T>>>(row, col, E);

    const int gy = (N + 127) / 128;
    const int ab = (N + 7) / 8;   // agg blocks: 8 warps/block, 1 warp/node

    // Layer 0: K=128, NBF=128, Ntot=224, out 256 + relu
    k_gemm<<<dim3(2, gy), 256>>>(x, Wb0, Wc0, bc0, lin, N, 128, 128, 224);
    k_agg<128, 32, true><<<ab, 256>>>(lin, 224, b0, hA, N);

    // Layer 1: K=256, NBF=128, Ntot=224, out 256 + relu
    k_gemm<<<dim3(2, gy), 256>>>(hA, Wb1, Wc1, bc1, lin, N, 256, 128, 224);
    k_agg<128, 32, true><<<ab, 256>>>(lin, 224, b1, hB, N);

    // Layer 2: K=256, NBF=176, Ntot=272, out 352, no relu
    k_gemm<<<dim3(3, gy), 256>>>(hB, Wb2, Wc2, bc2, lin, N, 256, 176, 272);
    k_agg<176, 44, false><<<ab, 256>>>(lin, 272, b2, hO, N);

    // log_softmax over first 349 columns
    k_lsm<<<ab, 256>>>(hO, (float*)d_out, N);
}

// round 2
// speedup vs baseline: 2.1320x; 2.1320x over previous
#include <cuda_runtime.h>
#include <math.h>
#include <stdint.h>

#define NMAX   50000
#define EMAX   600000
#define HIDW   256
#define OUTW   352
#define OUTT   349
#define MAXNTOT 272

// ---------------- scratch (device globals) ----------------------------------
__device__ int   g_deg[NMAX];
__device__ float g_dinv[NMAX];
__device__ int   g_off[NMAX + 1];
__device__ int   g_cur[NMAX];
__device__ int   g_adj[EMAX];
__device__ int   g_bsum[256];
__device__ float g_lin[(size_t)NMAX * MAXNTOT];
__device__ float g_hA[(size_t)NMAX * HIDW];
__device__ float g_hB[(size_t)NMAX * HIDW];
__device__ float g_hO[(size_t)NMAX * OUTW];

// ---------------- CSR build --------------------------------------------------
__global__ void k_zero(int n) {
    int i = blockIdx.x * blockDim.x + threadIdx.x;
    if (i < n) g_deg[i] = 0;
}

__global__ void k_deg(const int* __restrict__ row, int e) {
    int i = blockIdx.x * blockDim.x + threadIdx.x;
    if (i < e) atomicAdd(&g_deg[row[i]], 1);
}

__global__ void k_dinv(int n) {
    int i = blockIdx.x * blockDim.x + threadIdx.x;
    if (i < n) {
        int d = g_deg[i];
        g_dinv[i] = (d > 0) ? rsqrtf((float)d) : 0.0f;
    }
}

// block partial sums
__global__ void k_scan1(int n) {
    __shared__ int sh[256];
    int t = threadIdx.x;
    int i = blockIdx.x * 256 + t;
    sh[t] = (i < n) ? g_deg[i] : 0;
    __syncthreads();
#pragma unroll
    for (int s = 128; s; s >>= 1) {
        if (t < s) sh[t] += sh[t + s];
        __syncthreads();
    }
    if (t == 0) g_bsum[blockIdx.x] = sh[0];
}

// exclusive scan of block sums (nb <= 256)
__global__ void k_scan2(int nb) {
    __shared__ int sh[256];
    int t = threadIdx.x;
    int v = (t < nb) ? g_bsum[t] : 0;
    sh[t] = v;
    __syncthreads();
#pragma unroll
    for (int d = 1; d < 256; d <<= 1) {
        int u = (t >= d) ? sh[t - d] : 0;
        __syncthreads();
        sh[t] += u;
        __syncthreads();
    }
    if (t < nb) g_bsum[t] = sh[t] - v;   // exclusive
}

// per-block exclusive scan + base -> offsets
__global__ void k_scan3(int n, int total) {
    __shared__ int sh[256];
    int t = threadIdx.x;
    int i = blockIdx.x * 256 + t;
    int v = (i < n) ? g_deg[i] : 0;
    sh[t] = v;
    __syncthreads();
#pragma unroll
    for (int d = 1; d < 256; d <<= 1) {
        int u = (t >= d) ? sh[t - d] : 0;
        __syncthreads();
        sh[t] += u;
        __syncthreads();
    }
    int excl = sh[t] - v + g_bsum[blockIdx.x];
    if (i < n) { g_off[i] = excl; g_cur[i] = excl; }
    if (blockIdx.x == 0 && t == 0) g_off[n] = total;
}

__global__ void k_scatter(const int* __restrict__ row, const int* __restrict__ col, int e) {
    int i = blockIdx.x * blockDim.x + threadIdx.x;
    if (i < e) {
        int r = row[i];
        int p = atomicAdd(&g_cur[r], 1);
        g_adj[p] = col[i];
    }
}

// ---------------- GEMM: lin = h @ [Wb | Wc] + [0 | bc] -----------------------
// 128 x (16*UW) tile, BK=16, 256 threads, 8 x UW micro-tile, double-buffered.
__device__ __forceinline__ float4 ld4(const float* p) {
    return p ? __ldg(reinterpret_cast<const float4*>(p))
             : make_float4(0.f, 0.f, 0.f, 0.f);
}

template<int UW>
__global__ __launch_bounds__(256)
void k_gemm(const float* __restrict__ A, const float* __restrict__ Wb,
            const float* __restrict__ Wc, const float* __restrict__ bc,
            float* __restrict__ C, int M, int K, int NBF, int Ntot)
{
    constexpr int BN  = 16 * UW;
    constexpr int NB4 = BN / 4;       // float4 per k-row of B tile
    constexpr int TB4 = 16 * NB4;     // total B float4 per tile

    __shared__ __align__(16) float As[2][16][132];
    __shared__ __align__(16) float Bs[2][16][BN];

    const int bm  = blockIdx.y * 128;
    const int bn  = blockIdx.x * BN;
    const int tid = threadIdx.x;
    const int tx  = tid & 15;
    const int ty  = tid >> 4;
    const int cw  = Ntot - NBF;

    // --- A prefetch lanes: 2 float4 per thread (128 rows x 4 f4) ---
    int am[2], ak[2];
    const float* pa[2];
#pragma unroll
    for (int j = 0; j < 2; j++) {
        int id = tid + j * 256;
        am[j] = id >> 2;
        ak[j] = (id & 3) * 4;
        int gm = bm + am[j];
        pa[j] = (gm < M) ? A + (size_t)gm * K + ak[j] : nullptr;
    }

    // --- B prefetch lanes: up to 2 float4 per thread ---
    int bkk[2], bnq[2];
    bool bval[2];
    const float* pb[2];
    int bpit[2];
#pragma unroll
    for (int j = 0; j < 2; j++) {
        int id = tid + j * 256;
        bval[j] = (id < TB4);
        int kk = bval[j] ? id / NB4 : 0;
        int nq = bval[j] ? id % NB4 : 0;
        bkk[j] = kk; bnq[j] = nq;
        int gn4 = bn + nq * 4;
        pb[j] = nullptr; bpit[j] = 0;
        if (bval[j]) {
            if (gn4 < NBF)       { pb[j] = Wb + (size_t)kk * NBF + gn4;          bpit[j] = NBF; }
            else if (gn4 < Ntot) { pb[j] = Wc + (size_t)kk * cw  + (gn4 - NBF);  bpit[j] = cw;  }
        }
    }

    float acc[8][UW];
#pragma unroll
    for (int r = 0; r < 8; r++)
#pragma unroll
        for (int c = 0; c < UW; c++) acc[r][c] = 0.0f;

    float4 ra[2], rb[2];
#pragma unroll
    for (int j = 0; j < 2; j++) { ra[j] = ld4(pa[j]); rb[j] = ld4(pb[j]); }

    int buf = 0;
    // store tile 0
#pragma unroll
    for (int j = 0; j < 2; j++) {
        As[buf][ak[j] + 0][am[j]] = ra[j].x;
        As[buf][ak[j] + 1][am[j]] = ra[j].y;
        As[buf][ak[j] + 2][am[j]] = ra[j].z;
        As[buf][ak[j] + 3][am[j]] = ra[j].w;
        if (bval[j]) *reinterpret_cast<float4*>(&Bs[buf][bkk[j]][bnq[j] * 4]) = rb[j];
    }
    __syncthreads();

    const int kiter = K >> 4;
    for (int it = 1; it < kiter; it++) {
        // issue next-tile global loads
#pragma unroll
        for (int j = 0; j < 2; j++) {
            if (pa[j]) pa[j] += 16;
            if (pb[j]) pb[j] += (size_t)bpit[j] * 16;
            ra[j] = ld4(pa[j]);
            rb[j] = ld4(pb[j]);
        }
        // compute current buffer
#pragma unroll
        for (int kk = 0; kk < 16; kk++) {
            float a[8], b[UW];
#pragma unroll
            for (int r = 0; r < 8; r++)  a[r] = As[buf][kk][ty * 8 + r];
#pragma unroll
            for (int c = 0; c < UW; c++) b[c] = Bs[buf][kk][tx * UW + c];
#pragma unroll
            for (int r = 0; r < 8; r++)
#pragma unroll
                for (int c = 0; c < UW; c++)
                    acc[r][c] = fmaf(a[r], b[c], acc[r][c]);
        }
        // store next buffer
        int nb = buf ^ 1;
#pragma unroll
        for (int j = 0; j < 2; j++) {
            As[nb][ak[j] + 0][am[j]] = ra[j].x;
            As[nb][ak[j] + 1][am[j]] = ra[j].y;
            As[nb][ak[j] + 2][am[j]] = ra[j].z;
            As[nb][ak[j] + 3][am[j]] = ra[j].w;
            if (bval[j]) *reinterpret_cast<float4*>(&Bs[nb][bkk[j]][bnq[j] * 4]) = rb[j];
        }
        __syncthreads();
        buf = nb;
    }
    // last tile compute
#pragma unroll
    for (int kk = 0; kk < 16; kk++) {
        float a[8], b[UW];
#pragma unroll
        for (int r = 0; r < 8; r++)  a[r] = As[buf][kk][ty * 8 + r];
#pragma unroll
        for (int c = 0; c < UW; c++) b[c] = Bs[buf][kk][tx * UW + c];
#pragma unroll
        for (int r = 0; r < 8; r++)
#pragma unroll
            for (int c = 0; c < UW; c++)
                acc[r][c] = fmaf(a[r], b[c], acc[r][c]);
    }

    // epilogue
#pragma unroll
    for (int r = 0; r < 8; r++) {
        int gm = bm + ty * 8 + r;
        if (gm >= M) continue;
#pragma unroll
        for (int c = 0; c < UW; c++) {
            int gn = bn + tx * UW + c;
            if (gn < Ntot) {
                float v = acc[r][c];
                if (gn >= NBF) v += bc[gn - NBF];
                C[(size_t)gm * Ntot + gn] = v;
            }
        }
    }
}

// ---------------- fused aggregation + combine + bias (+relu) ----------------
template<int NBF, int F, bool RELU>
__global__ __launch_bounds__(256)
void k_agg(const float* __restrict__ lin, int stride,
           const float* __restrict__ bias,
           float* __restrict__ out, int n)
{
    constexpr int HF  = 8 * F;
    constexpr int C4  = (NBF + 127) / 128;
    constexpr int NF4 = NBF / 4;
    __shared__ float agg_s[8][3 * NBF];
    __shared__ float comb_s[8][96];

    int gw   = (blockIdx.x * 256 + threadIdx.x) >> 5;
    int lane = threadIdx.x & 31;
    int lw   = threadIdx.x >> 5;
    if (gw >= n) return;

    int s = g_off[gw], e = g_off[gw + 1];
    int deg = e - s;

    float4 vsym[C4], vsum[C4], vmax[C4];
#pragma unroll
    for (int q = 0; q < C4; q++) {
        vsym[q] = make_float4(0.f, 0.f, 0.f, 0.f);
        vsum[q] = make_float4(0.f, 0.f, 0.f, 0.f);
        vmax[q] = make_float4(-INFINITY, -INFINITY, -INFINITY, -INFINITY);
    }

    int t = s;
    for (; t + 2 <= e; t += 2) {
        int c0 = g_adj[t], c1 = g_adj[t + 1];
        float d0 = g_dinv[c0], d1 = g_dinv[c1];
        const float4* s0 = reinterpret_cast<const float4*>(lin + (size_t)c0 * stride);
        const float4* s1 = reinterpret_cast<const float4*>(lin + (size_t)c1 * stride);
#pragma unroll
        for (int q = 0; q < C4; q++) {
            int i4 = lane + q * 32;
            if (C4 > 1 && i4 >= NF4) break;
            float4 v0 = s0[i4];
            float4 v1 = s1[i4];
            vsym[q].x += d0 * v0.x + d1 * v1.x;
            vsym[q].y += d0 * v0.y + d1 * v1.y;
            vsym[q].z += d0 * v0.z + d1 * v1.z;
            vsym[q].w += d0 * v0.w + d1 * v1.w;
            vsum[q].x += v0.x + v1.x;
            vsum[q].y += v0.y + v1.y;
            vsum[q].z += v0.z + v1.z;
            vsum[q].w += v0.w + v1.w;
            vmax[q].x = fmaxf(vmax[q].x, fmaxf(v0.x, v1.x));
            vmax[q].y = fmaxf(vmax[q].y, fmaxf(v0.y, v1.y));
            vmax[q].z = fmaxf(vmax[q].z, fmaxf(v0.z, v1.z));
            vmax[q].w = fmaxf(vmax[q].w, fmaxf(v0.w, v1.w));
        }
    }
    if (t < e) {
        int c0 = g_adj[t];
        float d0 = g_dinv[c0];
        const float4* s0 = reinterpret_cast<const float4*>(lin + (size_t)c0 * stride);
#pragma unroll
        for (int q = 0; q < C4; q++) {
            int i4 = lane + q * 32;
            if (C4 > 1 && i4 >= NF4) break;
            float4 v0 = s0[i4];
            vsym[q].x += d0 * v0.x; vsym[q].y += d0 * v0.y;
            vsym[q].z += d0 * v0.z; vsym[q].w += d0 * v0.w;
            vsum[q].x += v0.x; vsum[q].y += v0.y;
            vsum[q].z += v0.z; vsum[q].w += v0.w;
            vmax[q].x = fmaxf(vmax[q].x, v0.x); vmax[q].y = fmaxf(vmax[q].y, v0.y);
            vmax[q].z = fmaxf(vmax[q].z, v0.z); vmax[q].w = fmaxf(vmax[q].w, v0.w);
        }
    }

    float dn   = g_dinv[gw];
    float invd = (deg > 0) ? (1.0f / (float)deg) : 0.0f;

    float4* arow0 = reinterpret_cast<float4*>(&agg_s[lw][0]);
    float4* arow1 = reinterpret_cast<float4*>(&agg_s[lw][NBF]);
    float4* arow2 = reinterpret_cast<float4*>(&agg_s[lw][2 * NBF]);
#pragma unroll
    for (int q = 0; q < C4; q++) {
        int i4 = lane + q * 32;
        if (C4 > 1 && i4 >= NF4) break;
        float4 sy = vsym[q];
        sy.x *= dn; sy.y *= dn; sy.z *= dn; sy.w *= dn;
        float4 me = vsum[q];
        me.x *= invd; me.y *= invd; me.z *= invd; me.w *= invd;
        float4 mx = vmax[q];
        if (deg == 0) mx = make_float4(0.f, 0.f, 0.f, 0.f);
        arow0[i4] = sy;
        arow1[i4] = me;
        arow2[i4] = mx;
    }

    const float* comb = lin + (size_t)gw * stride + NBF;
    comb_s[lw][lane]      = comb[lane];
    comb_s[lw][lane + 32] = comb[lane + 32];
    comb_s[lw][lane + 64] = comb[lane + 64];
    __syncwarp();

#pragma unroll
    for (int c = lane; c < HF; c += 32) {
        int h = c / F, f = c % F;
        float v = bias[c];
        const float* cb = &comb_s[lw][h * 12];
        const float* ag = &agg_s[lw][0];
#pragma unroll
        for (int k = 0; k < 12; k++) v = fmaf(cb[k], ag[k * F + f], v);
        if (RELU) v = fmaxf(v, 0.0f);
        out[(size_t)gw * HF + c] = v;
    }
}

// ---------------- log_softmax over first OUTT cols ---------------------------
__global__ __launch_bounds__(256)
void k_lsm(const float* __restrict__ in, float* __restrict__ out, int n)
{
    int gw   = (blockIdx.x * 256 + threadIdx.x) >> 5;
    int lane = threadIdx.x & 31;
    if (gw >= n) return;
    const float* r = in + (size_t)gw * OUTW;
    float v[11];
    float m = -INFINITY;
#pragma unroll
    for (int i = 0; i < 11; i++) {
        int c = lane + i * 32;
        v[i] = (c < OUTT) ? r[c] : -INFINITY;
        m = fmaxf(m, v[i]);
    }
#pragma unroll
    for (int o = 16; o; o >>= 1) m = fmaxf(m, __shfl_xor_sync(0xffffffffu, m, o));
    float s = 0.0f;
#pragma unroll
    for (int i = 0; i < 11; i++) s += expf(v[i] - m);
#pragma unroll
    for (int o = 16; o; o >>= 1) s += __shfl_xor_sync(0xffffffffu, s, o);
    float l = m + logf(s);
#pragma unroll
    for (int i = 0; i < 11; i++) {
        int c = lane + i * 32;
        if (c < OUTT) out[(size_t)gw * OUTT + c] = v[i] - l;
    }
}

// ---------------- launch ------------------------------------------------------
extern "C" void kernel_launch(void* const* d_in, const int* in_sizes, int n_in,
                              void* d_out, int out_size)
{
    const float* x   = (const float*)d_in[0];
    const int*   ei  = (const int*)d_in[1];
    int N = in_sizes[0] / 128;
    int E = in_sizes[1] / 2;
    if (N > NMAX) N = NMAX;
    if (E > EMAX) E = EMAX;
    const int* row = ei;
    const int* col = ei + E;

    const float* Wb0 = (const float*)d_in[2];
    const float* Wc0 = (const float*)d_in[3];
    const float* bc0 = (const float*)d_in[4];
    const float* b0  = (const float*)d_in[5];
    const float* Wb1 = (const float*)d_in[6];
    const float* Wc1 = (const float*)d_in[7];
    const float* bc1 = (const float*)d_in[8];
    const float* b1  = (const float*)d_in[9];
    const float* Wb2 = (const float*)d_in[10];
    const float* Wc2 = (const float*)d_in[11];
    const float* bc2 = (const float*)d_in[12];
    const float* b2  = (const float*)d_in[13];

    float* lin; float* hA; float* hB; float* hO;
    cudaGetSymbolAddress((void**)&lin, g_lin);
    cudaGetSymbolAddress((void**)&hA,  g_hA);
    cudaGetSymbolAddress((void**)&hB,  g_hB);
    cudaGetSymbolAddress((void**)&hO,  g_hO);

    const int T  = 256;
    const int gy = (N + 127) / 128;
    const int ab = (N + 7) / 8;
    const int sb = (N + 255) / 256;

    // CSR build interleaved with layer-0 GEMM (gemm0 independent of CSR)
    k_zero   <<<(N + T - 1) / T, T>>>(N);
    k_deg    <<<(E + T - 1) / T, T>>>(row, E);
    k_dinv   <<<(N + T - 1) / T, T>>>(N);
    k_gemm<7><<<dim3(2, gy), 256>>>(x, Wb0, Wc0, bc0, lin, N, 128, 128, 224);
    k_scan1  <<<sb, 256>>>(N);
    k_scan2  <<<1, 256>>>(sb);
    k_scan3  <<<sb, 256>>>(N, E);
    k_scatter<<<(E + T - 1) / T, T>>>(row, col, E);

    // Layer 0 aggregation (BN=112 tiles: 224 = 2x112, zero pad waste)
    k_agg<128, 32, true><<<ab, 256>>>(lin, 224, b0, hA, N);

    // Layer 1
    k_gemm<7><<<dim3(2, gy), 256>>>(hA, Wb1, Wc1, bc1, lin, N, 256, 128, 224);
    k_agg<128, 32, true><<<ab, 256>>>(lin, 224, b1, hB, N);

    // Layer 2 (BN=96 tiles: 272 -> 288, minimal pad)
    k_gemm<6><<<dim3(3, gy), 256>>>(hB, Wb2, Wc2, bc2, lin, N, 256, 176, 272);
    k_agg<176, 44, false><<<ab, 256>>>(lin, 272, b2, hO, N);

    k_lsm<<<ab, 256>>>(hO, (float*)d_out, N);
}

// round 3
// speedup vs baseline: 3.8095x; 1.7868x over previous
#include <cuda_runtime.h>
#include <math.h>
#include <stdint.h>

#define NMAX   50000
#define EMAX   600000
#define HIDW   256
#define OUTW   352
#define OUTT   349
#define MAXNTOT 272

// ---------------- scratch (device globals) ----------------------------------
__device__ int   g_deg[NMAX];
__device__ float g_dinv[NMAX];
__device__ int   g_off[NMAX + 1];
__device__ int   g_cur[NMAX];
__device__ int   g_adj[EMAX];
__device__ int   g_bsum[256];
__device__ float g_lin[(size_t)NMAX * MAXNTOT];
__device__ float g_hA[(size_t)NMAX * HIDW];
__device__ float g_hB[(size_t)NMAX * HIDW];
__device__ float g_hO[(size_t)NMAX * OUTW];

// ---------------- CSR build --------------------------------------------------
__global__ void k_zero(int n) {
    int i = blockIdx.x * blockDim.x + threadIdx.x;
    if (i < n) g_deg[i] = 0;
}

__global__ void k_deg(const int* __restrict__ row, int e) {
    int i = blockIdx.x * blockDim.x + threadIdx.x;
    if (i < e) atomicAdd(&g_deg[row[i]], 1);
}

__global__ void k_dinv(int n) {
    int i = blockIdx.x * blockDim.x + threadIdx.x;
    if (i < n) {
        int d = g_deg[i];
        g_dinv[i] = (d > 0) ? rsqrtf((float)d) : 0.0f;
    }
}

__global__ void k_scan1(int n) {
    __shared__ int sh[256];
    int t = threadIdx.x;
    int i = blockIdx.x * 256 + t;
    sh[t] = (i < n) ? g_deg[i] : 0;
    __syncthreads();
#pragma unroll
    for (int s = 128; s; s >>= 1) {
        if (t < s) sh[t] += sh[t + s];
        __syncthreads();
    }
    if (t == 0) g_bsum[blockIdx.x] = sh[0];
}

__global__ void k_scan2(int nb) {
    __shared__ int sh[256];
    int t = threadIdx.x;
    int v = (t < nb) ? g_bsum[t] : 0;
    sh[t] = v;
    __syncthreads();
#pragma unroll
    for (int d = 1; d < 256; d <<= 1) {
        int u = (t >= d) ? sh[t - d] : 0;
        __syncthreads();
        sh[t] += u;
        __syncthreads();
    }
    if (t < nb) g_bsum[t] = sh[t] - v;
}

__global__ void k_scan3(int n, int total) {
    __shared__ int sh[256];
    int t = threadIdx.x;
    int i = blockIdx.x * 256 + t;
    int v = (i < n) ? g_deg[i] : 0;
    sh[t] = v;
    __syncthreads();
#pragma unroll
    for (int d = 1; d < 256; d <<= 1) {
        int u = (t >= d) ? sh[t - d] : 0;
        __syncthreads();
        sh[t] += u;
        __syncthreads();
    }
    int excl = sh[t] - v + g_bsum[blockIdx.x];
    if (i < n) { g_off[i] = excl; g_cur[i] = excl; }
    if (blockIdx.x == 0 && t == 0) g_off[n] = total;
}

__global__ void k_scatter(const int* __restrict__ row, const int* __restrict__ col, int e) {
    int i = blockIdx.x * blockDim.x + threadIdx.x;
    if (i < e) {
        int r = row[i];
        int p = atomicAdd(&g_cur[r], 1);
        g_adj[p] = col[i];
    }
}

// ---------------- tf32 tensor-core GEMM --------------------------------------
// C[M,Ntot] = A[M,K] @ [Wb|Wc] + [0|bc].  BM=128, BN=16*NT, BK=16.
// 8 warps (4 m x 2 n); warp does 2x NT m16n8k8 tf32 MMAs per k-step of 8.
__device__ __forceinline__ uint32_t f2tf(float x) {
    uint32_t y;
    asm("cvt.rna.tf32.f32 %0, %1;" : "=r"(y) : "f"(x));
    return y;
}

__device__ __forceinline__ float4 ld4(const float* p) {
    return p ? __ldg(reinterpret_cast<const float4*>(p))
             : make_float4(0.f, 0.f, 0.f, 0.f);
}

__device__ __forceinline__ void mma8(float* c, const uint32_t* a, const uint32_t* b) {
    asm volatile(
        "mma.sync.aligned.m16n8k8.row.col.f32.tf32.tf32.f32 "
        "{%0,%1,%2,%3}, {%4,%5,%6,%7}, {%8,%9}, {%0,%1,%2,%3};"
        : "+f"(c[0]), "+f"(c[1]), "+f"(c[2]), "+f"(c[3])
        : "r"(a[0]), "r"(a[1]), "r"(a[2]), "r"(a[3]), "r"(b[0]), "r"(b[1]));
}

template<int NT>
__global__ __launch_bounds__(256)
void k_gemm_t(const float* __restrict__ A, const float* __restrict__ Wb,
              const float* __restrict__ Wc, const float* __restrict__ bc,
              float* __restrict__ C, int M, int K, int NBF, int Ntot)
{
    constexpr int BN  = 16 * NT;
    constexpr int BP  = BN + 8;     // B smem pitch (conflict-free frag loads)
    constexpr int NB4 = BN / 4;     // float4 per B k-row
    constexpr int TB4 = 16 * NB4;   // B float4 per tile

    __shared__ uint32_t As[2][128][20];   // [row][k], pitch 20
    __shared__ uint32_t Bs[2][16][BP];    // [k][n]

    const int tid  = threadIdx.x;
    const int bm   = blockIdx.y * 128;
    const int bn   = blockIdx.x * BN;
    const int w    = tid >> 5, lane = tid & 31;
    const int wm   = w & 3,   wn   = w >> 2;
    const int g    = lane >> 2, t4 = lane & 3;
    const int cw   = Ntot - NBF;

    // ---- A prefetch lanes: 2 float4/thread; id -> row=id>>2, kq=(id&3)*4 ----
    int am[2], ak[2];
    const float* pa[2];
#pragma unroll
    for (int j = 0; j < 2; j++) {
        int id = tid + j * 256;
        am[j] = id >> 2;
        ak[j] = (id & 3) * 4;
        int gm = bm + am[j];
        pa[j] = (gm < M) ? A + (size_t)gm * K + ak[j] : nullptr;
    }

    // ---- B prefetch lanes: up to 2 float4/thread from [Wb|Wc] ----
    int bkk[2], bnq[2];
    bool bval[2];
    const float* pb[2];
    int bpit[2];
#pragma unroll
    for (int j = 0; j < 2; j++) {
        int id = tid + j * 256;
        bval[j] = (id < TB4);
        int kk = bval[j] ? id / NB4 : 0;
        int nq = bval[j] ? id % NB4 : 0;
        bkk[j] = kk; bnq[j] = nq;
        int gn4 = bn + nq * 4;
        pb[j] = nullptr; bpit[j] = 0;
        if (bval[j]) {
            if (gn4 < NBF)       { pb[j] = Wb + (size_t)kk * NBF + gn4;         bpit[j] = NBF; }
            else if (gn4 < Ntot) { pb[j] = Wc + (size_t)kk * cw  + (gn4 - NBF); bpit[j] = cw;  }
        }
    }

    float acc[2][NT][4];
#pragma unroll
    for (int i = 0; i < 2; i++)
#pragma unroll
        for (int j = 0; j < NT; j++)
#pragma unroll
            for (int r = 0; r < 4; r++) acc[i][j][r] = 0.0f;

    float4 ra[2], rb[2];
#pragma unroll
    for (int j = 0; j < 2; j++) { ra[j] = ld4(pa[j]); rb[j] = ld4(pb[j]); }

    int buf = 0;
#pragma unroll
    for (int j = 0; j < 2; j++) {
        As[buf][am[j]][ak[j] + 0] = f2tf(ra[j].x);
        As[buf][am[j]][ak[j] + 1] = f2tf(ra[j].y);
        As[buf][am[j]][ak[j] + 2] = f2tf(ra[j].z);
        As[buf][am[j]][ak[j] + 3] = f2tf(ra[j].w);
        if (bval[j]) {
            Bs[buf][bkk[j]][bnq[j] * 4 + 0] = f2tf(rb[j].x);
            Bs[buf][bkk[j]][bnq[j] * 4 + 1] = f2tf(rb[j].y);
            Bs[buf][bkk[j]][bnq[j] * 4 + 2] = f2tf(rb[j].z);
            Bs[buf][bkk[j]][bnq[j] * 4 + 3] = f2tf(rb[j].w);
        }
    }
    __syncthreads();

    const int rm0 = wm * 32;
    const int cn0 = wn * NT * 8;
    const int kiter = K >> 4;

    for (int it = 1; it <= kiter; it++) {
        if (it < kiter) {
#pragma unroll
            for (int j = 0; j < 2; j++) {
                if (pa[j]) pa[j] += 16;
                if (pb[j]) pb[j] += (size_t)bpit[j] * 16;
                ra[j] = ld4(pa[j]);
                rb[j] = ld4(pb[j]);
            }
        }
        // compute current buffer: 2 k-steps of 8
#pragma unroll
        for (int ks = 0; ks < 2; ks++) {
            int k0 = ks * 8;
            uint32_t af[2][4], bf[NT][2];
#pragma unroll
            for (int i = 0; i < 2; i++) {
                int rm = rm0 + i * 16;
                af[i][0] = As[buf][rm + g][k0 + t4];
                af[i][1] = As[buf][rm + g + 8][k0 + t4];
                af[i][2] = As[buf][rm + g][k0 + t4 + 4];
                af[i][3] = As[buf][rm + g + 8][k0 + t4 + 4];
            }
#pragma unroll
            for (int j = 0; j < NT; j++) {
                bf[j][0] = Bs[buf][k0 + t4][cn0 + j * 8 + g];
                bf[j][1] = Bs[buf][k0 + t4 + 4][cn0 + j * 8 + g];
            }
#pragma unroll
            for (int i = 0; i < 2; i++)
#pragma unroll
                for (int j = 0; j < NT; j++)
                    mma8(acc[i][j], af[i], bf[j]);
        }
        if (it < kiter) {
            int nb = buf ^ 1;
#pragma unroll
            for (int j = 0; j < 2; j++) {
                As[nb][am[j]][ak[j] + 0] = f2tf(ra[j].x);
                As[nb][am[j]][ak[j] + 1] = f2tf(ra[j].y);
                As[nb][am[j]][ak[j] + 2] = f2tf(ra[j].z);
                As[nb][am[j]][ak[j] + 3] = f2tf(ra[j].w);
                if (bval[j]) {
                    Bs[nb][bkk[j]][bnq[j] * 4 + 0] = f2tf(rb[j].x);
                    Bs[nb][bkk[j]][bnq[j] * 4 + 1] = f2tf(rb[j].y);
                    Bs[nb][bkk[j]][bnq[j] * 4 + 2] = f2tf(rb[j].z);
                    Bs[nb][bkk[j]][bnq[j] * 4 + 3] = f2tf(rb[j].w);
                }
            }
            __syncthreads();
            buf = nb;
        }
    }

    // ---- epilogue: float2 stores, bias on comb columns ----
#pragma unroll
    for (int i = 0; i < 2; i++) {
        int r0 = bm + rm0 + i * 16 + g;
#pragma unroll
        for (int j = 0; j < NT; j++) {
            int col = bn + cn0 + j * 8 + 2 * t4;
            if (col >= Ntot) continue;
            float b0 = 0.f, b1 = 0.f;
            if (col >= NBF) { b0 = bc[col - NBF]; b1 = bc[col - NBF + 1]; }
            if (r0 < M) {
                float2 v = make_float2(acc[i][j][0] + b0, acc[i][j][1] + b1);
                *reinterpret_cast<float2*>(&C[(size_t)r0 * Ntot + col]) = v;
            }
            if (r0 + 8 < M) {
                float2 v = make_float2(acc[i][j][2] + b0, acc[i][j][3] + b1);
                *reinterpret_cast<float2*>(&C[(size_t)(r0 + 8) * Ntot + col]) = v;
            }
        }
    }
}

// ---------------- fused aggregation + combine + bias (+relu) ----------------
template<int NBF, int F, bool RELU>
__global__ __launch_bounds__(256)
void k_agg(const float* __restrict__ lin, int stride,
           const float* __restrict__ bias,
           float* __restrict__ out, int n)
{
    constexpr int HF  = 8 * F;
    constexpr int C4  = (NBF + 127) / 128;
    constexpr int NF4 = NBF / 4;
    __shared__ float agg_s[8][3 * NBF];
    __shared__ float comb_s[8][96];

    int gw   = (blockIdx.x * 256 + threadIdx.x) >> 5;
    int lane = threadIdx.x & 31;
    int lw   = threadIdx.x >> 5;
    if (gw >= n) return;

    int s = g_off[gw], e = g_off[gw + 1];
    int deg = e - s;

    float4 vsym[C4], vsum[C4], vmax[C4];
#pragma unroll
    for (int q = 0; q < C4; q++) {
        vsym[q] = make_float4(0.f, 0.f, 0.f, 0.f);
        vsum[q] = make_float4(0.f, 0.f, 0.f, 0.f);
        vmax[q] = make_float4(-INFINITY, -INFINITY, -INFINITY, -INFINITY);
    }

    int t = s;
    for (; t + 2 <= e; t += 2) {
        int c0 = g_adj[t], c1 = g_adj[t + 1];
        float d0 = g_dinv[c0], d1 = g_dinv[c1];
        const float4* s0 = reinterpret_cast<const float4*>(lin + (size_t)c0 * stride);
        const float4* s1 = reinterpret_cast<const float4*>(lin + (size_t)c1 * stride);
#pragma unroll
        for (int q = 0; q < C4; q++) {
            int i4 = lane + q * 32;
            if (C4 > 1 && i4 >= NF4) break;
            float4 v0 = s0[i4];
            float4 v1 = s1[i4];
            vsym[q].x += d0 * v0.x + d1 * v1.x;
            vsym[q].y += d0 * v0.y + d1 * v1.y;
            vsym[q].z += d0 * v0.z + d1 * v1.z;
            vsym[q].w += d0 * v0.w + d1 * v1.w;
            vsum[q].x += v0.x + v1.x;
            vsum[q].y += v0.y + v1.y;
            vsum[q].z += v0.z + v1.z;
            vsum[q].w += v0.w + v1.w;
            vmax[q].x = fmaxf(vmax[q].x, fmaxf(v0.x, v1.x));
            vmax[q].y = fmaxf(vmax[q].y, fmaxf(v0.y, v1.y));
            vmax[q].z = fmaxf(vmax[q].z, fmaxf(v0.z, v1.z));
            vmax[q].w = fmaxf(vmax[q].w, fmaxf(v0.w, v1.w));
        }
    }
    if (t < e) {
        int c0 = g_adj[t];
        float d0 = g_dinv[c0];
        const float4* s0 = reinterpret_cast<const float4*>(lin + (size_t)c0 * stride);
#pragma unroll
        for (int q = 0; q < C4; q++) {
            int i4 = lane + q * 32;
            if (C4 > 1 && i4 >= NF4) break;
            float4 v0 = s0[i4];
            vsym[q].x += d0 * v0.x; vsym[q].y += d0 * v0.y;
            vsym[q].z += d0 * v0.z; vsym[q].w += d0 * v0.w;
            vsum[q].x += v0.x; vsum[q].y += v0.y;
            vsum[q].z += v0.z; vsum[q].w += v0.w;
            vmax[q].x = fmaxf(vmax[q].x, v0.x); vmax[q].y = fmaxf(vmax[q].y, v0.y);
            vmax[q].z = fmaxf(vmax[q].z, v0.z); vmax[q].w = fmaxf(vmax[q].w, v0.w);
        }
    }

    float dn   = g_dinv[gw];
    float invd = (deg > 0) ? (1.0f / (float)deg) : 0.0f;

    float4* arow0 = reinterpret_cast<float4*>(&agg_s[lw][0]);
    float4* arow1 = reinterpret_cast<float4*>(&agg_s[lw][NBF]);
    float4* arow2 = reinterpret_cast<float4*>(&agg_s[lw][2 * NBF]);
#pragma unroll
    for (int q = 0; q < C4; q++) {
        int i4 = lane + q * 32;
        if (C4 > 1 && i4 >= NF4) break;
        float4 sy = vsym[q];
        sy.x *= dn; sy.y *= dn; sy.z *= dn; sy.w *= dn;
        float4 me = vsum[q];
        me.x *= invd; me.y *= invd; me.z *= invd; me.w *= invd;
        float4 mx = vmax[q];
        if (deg == 0) mx = make_float4(0.f, 0.f, 0.f, 0.f);
        arow0[i4] = sy;
        arow1[i4] = me;
        arow2[i4] = mx;
    }

    const float* comb = lin + (size_t)gw * stride + NBF;
    comb_s[lw][lane]      = comb[lane];
    comb_s[lw][lane + 32] = comb[lane + 32];
    comb_s[lw][lane + 64] = comb[lane + 64];
    __syncwarp();

#pragma unroll
    for (int c = lane; c < HF; c += 32) {
        int h = c / F, f = c % F;
        float v = bias[c];
        const float* cb = &comb_s[lw][h * 12];
        const float* ag = &agg_s[lw][0];
#pragma unroll
        for (int k = 0; k < 12; k++) v = fmaf(cb[k], ag[k * F + f], v);
        if (RELU) v = fmaxf(v, 0.0f);
        out[(size_t)gw * HF + c] = v;
    }
}

// ---------------- log_softmax -------------------------------------------------
__global__ __launch_bounds__(256)
void k_lsm(const float* __restrict__ in, float* __restrict__ out, int n)
{
    int gw   = (blockIdx.x * 256 + threadIdx.x) >> 5;
    int lane = threadIdx.x & 31;
    if (gw >= n) return;
    const float* r = in + (size_t)gw * OUTW;
    float v[11];
    float m = -INFINITY;
#pragma unroll
    for (int i = 0; i < 11; i++) {
        int c = lane + i * 32;
        v[i] = (c < OUTT) ? r[c] : -INFINITY;
        m = fmaxf(m, v[i]);
    }
#pragma unroll
    for (int o = 16; o; o >>= 1) m = fmaxf(m, __shfl_xor_sync(0xffffffffu, m, o));
    float s = 0.0f;
#pragma unroll
    for (int i = 0; i < 11; i++) s += expf(v[i] - m);
#pragma unroll
    for (int o = 16; o; o >>= 1) s += __shfl_xor_sync(0xffffffffu, s, o);
    float l = m + logf(s);
#pragma unroll
    for (int i = 0; i < 11; i++) {
        int c = lane + i * 32;
        if (c < OUTT) out[(size_t)gw * OUTT + c] = v[i] - l;
    }
}

// ---------------- launch --------------------------------------------------------
extern "C" void kernel_launch(void* const* d_in, const int* in_sizes, int n_in,
                              void* d_out, int out_size)
{
    const float* x   = (const float*)d_in[0];
    const int*   ei  = (const int*)d_in[1];
    int N = in_sizes[0] / 128;
    int E = in_sizes[1] / 2;
    if (N > NMAX) N = NMAX;
    if (E > EMAX) E = EMAX;
    const int* row = ei;
    const int* col = ei + E;

    const float* Wb0 = (const float*)d_in[2];
    const float* Wc0 = (const float*)d_in[3];
    const float* bc0 = (const float*)d_in[4];
    const float* b0  = (const float*)d_in[5];
    const float* Wb1 = (const float*)d_in[6];
    const float* Wc1 = (const float*)d_in[7];
    const float* bc1 = (const float*)d_in[8];
    const float* b1  = (const float*)d_in[9];
    const float* Wb2 = (const float*)d_in[10];
    const float* Wc2 = (const float*)d_in[11];
    const float* bc2 = (const float*)d_in[12];
    const float* b2  = (const float*)d_in[13];

    float* lin; float* hA; float* hB; float* hO;
    cudaGetSymbolAddress((void**)&lin, g_lin);
    cudaGetSymbolAddress((void**)&hA,  g_hA);
    cudaGetSymbolAddress((void**)&hB,  g_hB);
    cudaGetSymbolAddress((void**)&hO,  g_hO);

    const int T  = 256;
    const int gy = (N + 127) / 128;
    const int ab = (N + 7) / 8;
    const int sb = (N + 255) / 256;

    // CSR build interleaved with layer-0 GEMM (independent of CSR)
    k_zero   <<<(N + T - 1) / T, T>>>(N);
    k_deg    <<<(E + T - 1) / T, T>>>(row, E);
    k_dinv   <<<(N + T - 1) / T, T>>>(N);
    k_gemm_t<7><<<dim3(2, gy), 256>>>(x, Wb0, Wc0, bc0, lin, N, 128, 128, 224);
    k_scan1  <<<sb, 256>>>(N);
    k_scan2  <<<1, 256>>>(sb);
    k_scan3  <<<sb, 256>>>(N, E);
    k_scatter<<<(E + T - 1) / T, T>>>(row, col, E);

    k_agg<128, 32, true><<<ab, 256>>>(lin, 224, b0, hA, N);

    k_gemm_t<7><<<dim3(2, gy), 256>>>(hA, Wb1, Wc1, bc1, lin, N, 256, 128, 224);
    k_agg<128, 32, true><<<ab, 256>>>(lin, 224, b1, hB, N);

    k_gemm_t<6><<<dim3(3, gy), 256>>>(hB, Wb2, Wc2, bc2, lin, N, 256, 176, 272);
    k_agg<176, 44, false><<<ab, 256>>>(lin, 272, b2, hO, N);

    k_lsm<<<ab, 256>>>(hO, (float*)d_out, N);
}